// round 11
// baseline (speedup 1.0000x reference)
#include <cuda_runtime.h>
#include <cuda_bf16.h>
#include <math.h>

// pred/target: (32, 3, 512, 512) fp32 -> scalar fp32 mean |sobel(gray(p)) - sobel(gray(t))|
#define B      32
#define H      512
#define W      512
#define PLANE  (H * W)
#define IMG    (3 * PLANE)
#define NPIX   (B * PLANE)            // 8388608

#define RT     16                     // rows per CTA tile
#define TILESY (H / RT)               // 32
#define NBLK   (B * TILESY)           // 1024
#define TPB    128                    // 4 warps; warp w owns cols [128w, 128w+128)
#define FULLM  0xffffffffu

__device__ float        g_partials[NBLK];
__device__ unsigned int g_count = 0;

__device__ __forceinline__ float fsqrt_approx(float x) {
    float r; asm("sqrt.approx.f32 %0, %1;" : "=f"(r) : "f"(x)); return r;
}

__global__ __launch_bounds__(TPB, 5) void edge_loss_fused(
    const float* __restrict__ pred, const float* __restrict__ tgt,
    float* __restrict__ out)
{
    const int tid  = threadIdx.x;
    const int w    = tid >> 5;
    const int lane = tid & 31;
    const int tile = blockIdx.x;
    const int b    = blockIdx.y;
    const int gy0  = tile * RT;
    const int cb   = w * 128 + lane * 4;     // this thread's first column

    const float* pr = pred + (size_t)b * IMG;
    const float* tr = tgt  + (size_t)b * IMG;

    // Edge roles: lane 0 fetches gray(col cb-1), lane 31 fetches gray(col cb+4),
    // for both images (warp-boundary halo; L1/L2-resident lines).
    const bool eleft = (lane == 0);
    const int  ec    = eleft ? (cb - 1) : (cb + 4);
    const bool ehas  = (lane == 0 || lane == 31) &&
                       (eleft ? (cb > 0) : (cb + 4 < W));

    float4 Pr, Pg, Pb, Tr, Tg, Tb;   // prefetched rgb quads (both images)
    float  egp = 0.f, egt = 0.f;     // prefetched edge grays (lanes 0/31)

#define LOAD(gy) do {                                                        \
        if ((unsigned)(gy) < (unsigned)H) {                                  \
            const float* _p = pr + (size_t)(gy) * W + cb;                    \
            Pr = *(const float4*)_p;                                         \
            Pg = *(const float4*)(_p + PLANE);                               \
            Pb = *(const float4*)(_p + 2 * PLANE);                           \
            const float* _t = tr + (size_t)(gy) * W + cb;                    \
            Tr = *(const float4*)_t;                                         \
            Tg = *(const float4*)(_t + PLANE);                               \
            Tb = *(const float4*)(_t + 2 * PLANE);                           \
            if (ehas) {                                                      \
                const int _eo = (gy) * W + ec;                               \
                egp = 0.299f * pr[_eo] + 0.587f * pr[_eo + PLANE]            \
                    + 0.114f * pr[_eo + 2 * PLANE];                          \
                egt = 0.299f * tr[_eo] + 0.587f * tr[_eo + PLANE]            \
                    + 0.114f * tr[_eo + 2 * PLANE];                          \
            } else { egp = 0.f; egt = 0.f; }                                 \
        } else {                                                             \
            Pr = Pg = Pb = make_float4(0.f, 0.f, 0.f, 0.f);                  \
            Tr = Tg = Tb = make_float4(0.f, 0.f, 0.f, 0.f);                  \
            egp = 0.f; egt = 0.f;                                            \
        }                                                                    \
    } while (0)

    // Rolling separable state: windows j = 0..3 (img0 cols), 4..7 (img1 cols).
    float HX0[8], HX1[8], HS0[8], HS1[8];

    // Convert prefetch -> 6-wide gray windows (shuffle boundaries) -> hx2/hs2.
    // hx2/hs2 land in caller-provided arrays; does NOT touch rolling state.
#define CONV(HX2, HS2, NEXTLOAD) do {                                        \
        float a0 = 0.299f * Pr.x + 0.587f * Pg.x + 0.114f * Pb.x;            \
        float a1 = 0.299f * Pr.y + 0.587f * Pg.y + 0.114f * Pb.y;            \
        float a2 = 0.299f * Pr.z + 0.587f * Pg.z + 0.114f * Pb.z;            \
        float a3 = 0.299f * Pr.w + 0.587f * Pg.w + 0.114f * Pb.w;            \
        float c0 = 0.299f * Tr.x + 0.587f * Tg.x + 0.114f * Tb.x;            \
        float c1 = 0.299f * Tr.y + 0.587f * Tg.y + 0.114f * Tb.y;            \
        float c2 = 0.299f * Tr.z + 0.587f * Tg.z + 0.114f * Tb.z;            \
        float c3 = 0.299f * Tr.w + 0.587f * Tg.w + 0.114f * Tb.w;            \
        float al = __shfl_up_sync(FULLM, a3, 1);                             \
        float ar = __shfl_down_sync(FULLM, a0, 1);                           \
        float cl = __shfl_up_sync(FULLM, c3, 1);                             \
        float cr = __shfl_down_sync(FULLM, c0, 1);                           \
        if (lane == 0)  { al = egp; cl = egt; }                              \
        if (lane == 31) { ar = egp; cr = egt; }                              \
        NEXTLOAD;                                                            \
        float wa[6] = { al, a0, a1, a2, a3, ar };                            \
        float wc[6] = { cl, c0, c1, c2, c3, cr };                            \
        _Pragma("unroll")                                                    \
        for (int j = 0; j < 4; j++) {                                        \
            (HX2)[j]     = wa[j + 2] - wa[j];                                \
            (HS2)[j]     = wa[j] + 2.f * wa[j + 1] + wa[j + 2];              \
            (HX2)[j + 4] = wc[j + 2] - wc[j];                                \
            (HS2)[j + 4] = wc[j] + 2.f * wc[j + 1] + wc[j + 2];              \
        }                                                                    \
    } while (0)

    // ---- Prologue: rows gy0-1 -> state0, gy0 -> state1; prefetch gy0+1 ----
    LOAD(gy0 - 1);
    CONV(HX0, HS0, LOAD(gy0));
    CONV(HX1, HS1, LOAD(gy0 + 1));

    // ---- Mainloop: no smem, no barriers. conv(r+1) -> LDG(r+2) -> compute(r) ----
    float acc = 0.f;
    #pragma unroll 2
    for (int r = 0; r < RT; r++) {
        float HX2[8], HS2[8];
        if (r < RT - 1) {
            CONV(HX2, HS2, LOAD(gy0 + r + 2));
        } else {
            CONV(HX2, HS2, );
        }
        float mag[8];
        #pragma unroll
        for (int j = 0; j < 8; j++) {
            float ex = HX0[j] + 2.f * HX1[j] + HX2[j];
            float ey = HS2[j] - HS0[j];
            mag[j] = fsqrt_approx(ex * ex + ey * ey);
            HX0[j] = HX1[j]; HX1[j] = HX2[j];
            HS0[j] = HS1[j]; HS1[j] = HS2[j];
        }
        acc += fabsf(mag[0] - mag[4]) + fabsf(mag[1] - mag[5])
             + fabsf(mag[2] - mag[6]) + fabsf(mag[3] - mag[7]);
    }
#undef LOAD
#undef CONV

    // ---- Block reduction (fixed order, 4 warps) ----
    #pragma unroll
    for (int off = 16; off > 0; off >>= 1)
        acc += __shfl_down_sync(FULLM, acc, off);

    __shared__ float wsum[4];
    __shared__ bool  isLast;
    if (lane == 0) wsum[w] = acc;
    __syncthreads();
    if (tid < 4) {
        float v = wsum[tid];
        v += __shfl_down_sync(0x0000000fu, v, 2);
        v += __shfl_down_sync(0x0000000fu, v, 1);
        if (tid == 0) {
            g_partials[b * TILESY + tile] = v;
            __threadfence();
            unsigned int old = atomicAdd(&g_count, 1u);
            isLast = (old == (unsigned)(NBLK - 1));
        }
    }
    __syncthreads();

    // ---- Fused deterministic final reduction (last block, fp64 fixed order) ----
    if (isLast) {
        __shared__ double ds[TPB];
        double a = 0.0;
        #pragma unroll
        for (int i = 0; i < NBLK / TPB; i++)
            a += (double)__ldcg(&g_partials[tid + i * TPB]);
        ds[tid] = a;
        __syncthreads();
        #pragma unroll
        for (int st = TPB / 2; st > 0; st >>= 1) {
            if (tid < st) ds[tid] += ds[tid + st];
            __syncthreads();
        }
        if (tid == 0) {
            out[0] = (float)(ds[0] / (double)NPIX);
            g_count = 0;   // self-reset for graph replay
        }
    }
}

extern "C" void kernel_launch(void* const* d_in, const int* in_sizes, int n_in,
                              void* d_out, int out_size)
{
    const float* pred = (const float*)d_in[0];
    const float* tgt  = (const float*)d_in[1];
    float* out = (float*)d_out;

    dim3 grid(TILESY, B);   // (32, 32) = 1024 blocks
    edge_loss_fused<<<grid, TPB>>>(pred, tgt, out);
}

// round 14
// speedup vs baseline: 1.1904x; 1.1904x over previous
#include <cuda_runtime.h>
#include <cuda_bf16.h>
#include <math.h>

// pred/target: (32, 3, 512, 512) fp32 -> scalar fp32 mean |sobel(gray(p)) - sobel(gray(t))|
#define B      32
#define H      512
#define W      512
#define PLANE  (H * W)
#define IMG    (3 * PLANE)
#define NPIX   (B * PLANE)            // 8388608

#define RT     32                     // rows per CTA tile
#define TILESY (H / RT)               // 16
#define NBLK   (B * TILESY)           // 512
#define TPB    256
#define SROW   520                    // gray slot stride; data at [4..515], zeros at 3/516

// RGB ring geometry: [slot 0..2][img 0/1][ch 0..2][512 floats]
#define SLOT_F   3072                 // floats per RGB slot (2*3*512)
#define SLOT_B   12288u               // bytes per RGB slot
#define IMG_F    1536                 // floats per image within a slot (3*512)
#define CH_B     2048u                // bytes per channel (512 floats)

__device__ float        g_partials[NBLK];
__device__ unsigned int g_count = 0;

__device__ __forceinline__ float fsqrt_approx(float x) {
    float r; asm("sqrt.approx.f32 %0, %1;" : "=f"(r) : "f"(x)); return r;
}

#define CP16(dst, src) \
    asm volatile("cp.async.cg.shared.global [%0], [%1], 16;" :: "r"(dst), "l"(src))
#define CP_COMMIT() asm volatile("cp.async.commit_group;" ::: "memory")
#define CP_WAIT(n)  asm volatile("cp.async.wait_group %0;" :: "n"(n) : "memory")

__device__ __forceinline__ float4 gray4(float4 r, float4 g, float4 bl)
{
    float4 v;
    v.x = 0.299f * r.x + 0.587f * g.x + 0.114f * bl.x;
    v.y = 0.299f * r.y + 0.587f * g.y + 0.114f * bl.y;
    v.z = 0.299f * r.z + 0.587f * g.z + 0.114f * bl.z;
    v.w = 0.299f * r.w + 0.587f * g.w + 0.114f * bl.w;
    return v;
}

// Horizontal separable partials at column c of a gray slot.
__device__ __forceinline__ void rdrow(const float* __restrict__ base, int c,
                                      float& hx, float& hs)
{
    float l  = base[3 + c];
    float m  = base[4 + c];
    float rr = base[5 + c];
    hx = rr - l;                 // [-1, 0, 1]
    hs = l + 2.f * m + rr;       // [ 1, 2, 1]
}

__global__ __launch_bounds__(TPB, 4) void edge_loss_fused(
    const float* __restrict__ pred, const float* __restrict__ tgt,
    float* __restrict__ out)
{
    // RGB ring: 3 slots x 2 imgs x 3 ch x 512 floats = 9216 floats (36 KB).
    __shared__ __align__(16) float rgb[3 * SLOT_F];
    // Gray ring: [img 0/1][slot 0/1][SROW]  (8.3 KB)
    __shared__ __align__(16) float gray[2 * 2 * SROW];

    const int tile = blockIdx.x;
    const int b    = blockIdx.y;
    const int gy0  = tile * RT;
    const int tid  = threadIdx.x;

    // Staging/convert role: thread handles quad q (4 cols) of image im.
    const int q  = tid & 127;
    const int im = tid >> 7;
    const float* simg = (im ? tgt : pred) + (size_t)b * IMG;

    // This thread's RGB smem target within slot 0 (generic and .shared addresses).
    float* rgb_g = rgb + im * IMG_F + 4 * q;
    const unsigned rgb_s = (unsigned)__cvta_generic_to_shared(rgb_g);
    float* gslotp[2] = { gray + im * 2 * SROW + 4 + 4 * q,
                         gray + im * 2 * SROW + SROW + 4 + 4 * q };

    // x-halo zeros for all 4 gray slots (never overwritten).
    if (tid < 4) { gray[tid * SROW + 3] = 0.f; gray[tid * SROW + 516] = 0.f; }

    // Issue async copy of row gy into RGB ring slot rs (zero STS if out of image;
    // those generic stores are ordered vs consumers by the same __syncthreads()).
#define ISSUE(gy, rs) do {                                                   \
        if ((unsigned)(gy) < (unsigned)H) {                                  \
            const float* _s = simg + (size_t)(gy) * W + 4 * q;               \
            const unsigned _d = rgb_s + (rs) * SLOT_B;                       \
            CP16(_d,          _s);                                           \
            CP16(_d + CH_B,   _s + PLANE);                                   \
            CP16(_d + 2*CH_B, _s + 2 * PLANE);                               \
        } else {                                                             \
            float4 _z = make_float4(0.f, 0.f, 0.f, 0.f);                     \
            float* _g = rgb_g + (rs) * SLOT_F;                               \
            *(float4*)_g = _z; *(float4*)(_g + 512) = _z;                    \
            *(float4*)(_g + 1024) = _z;                                      \
        }                                                                    \
    } while (0)

    // Convert RGB slot rs -> gray slot gs (this thread's quad, its image).
#define CONV(rs, gs) do {                                                    \
        const float* _b = rgb_g + (rs) * SLOT_F;                             \
        float4 _r = *(const float4*)_b;                                      \
        float4 _g = *(const float4*)(_b + 512);                              \
        float4 _l = *(const float4*)(_b + 1024);                             \
        *(float4*)(gslotp[gs]) = gray4(_r, _g, _l);                          \
    } while (0)

    // ---- Prologue.  Row k -> RGB slot (k+1)%3, gray slot k&1. ----
    ISSUE(gy0 - 1, 0);
    ISSUE(gy0,     1);
    CP_COMMIT();                 // G1: rows -1, 0
    ISSUE(gy0 + 1, 2);
    CP_COMMIT();                 // G2: row 1
    ISSUE(gy0 + 2, 0 /* (2+1)%3 */);
    CP_COMMIT();                 // G3: row 2
    CP_WAIT(2);                  // G1 done
    __syncthreads();
    CONV(0, 1);                  // gray(-1) -> s1
    CONV(1, 0);                  // gray( 0) -> s0
    __syncthreads();

    // Rolling windows. Combos j: img = j>>1, col = (j&1) ? tid+256 : tid.
    const int c0 = tid, c1 = tid + 256;
    float hx0[4], hx1[4], hs0[4], hs1[4];
    #pragma unroll
    for (int j = 0; j < 4; j++) {
        const float* base = gray + (j >> 1) * 2 * SROW;
        const int c = (j & 1) ? c1 : c0;
        rdrow(base + SROW, c, hx0[j], hs0[j]);   // row -1 (s1)
        rdrow(base,        c, hx1[j], hs1[j]);   // row  0 (s0)
    }
    CP_WAIT(1);                  // G2 done (row 1 landed)
    __syncthreads();             // also fences rolling reads of s1
    CONV(2, 1);                  // gray(1) -> s1

    // ---- Mainloop. Iter r: issue row r+3, wait(row r+2), bar,
    //      convert gray(r+2), compute row r from gray(r+1). ----
    float acc = 0.f;
    int cslot = 0;               // RGB slot of row r+2 = (r+3)%3; r=0 -> 0
    int islot = 1;               // RGB slot of row r+3 = (r+4)%3; r=0 -> 1
    #pragma unroll 2
    for (int r = 0; r < RT; r++) {
        if (r + 3 <= RT) ISSUE(gy0 + r + 3, islot);
        CP_COMMIT();             // empty group when skipped: keeps wait counts aligned
        CP_WAIT(1);              // row r+2 landed
        __syncthreads();

        const int gs = r & 1;            // gray slot of row r+2
        if (r < RT - 1) CONV(cslot, gs);

        const int rdslot = gs ^ 1;       // gray slot of row r+1
        float mag[4];
        #pragma unroll
        for (int j = 0; j < 4; j++) {
            const float* bnew = gray + (j >> 1) * 2 * SROW + rdslot * SROW;
            const int c = (j & 1) ? c1 : c0;
            float hx2, hs2;
            rdrow(bnew, c, hx2, hs2);
            float ex = hx0[j] + 2.f * hx1[j] + hx2;
            float ey = hs2 - hs0[j];
            mag[j] = fsqrt_approx(ex * ex + ey * ey);
            hx0[j] = hx1[j]; hx1[j] = hx2;
            hs0[j] = hs1[j]; hs1[j] = hs2;
        }
        acc += fabsf(mag[0] - mag[2]) + fabsf(mag[1] - mag[3]);

        cslot = (cslot == 2) ? 0 : cslot + 1;
        islot = (islot == 2) ? 0 : islot + 1;
    }
#undef ISSUE
#undef CONV

    // ---- Block reduction (fixed order) ----
    #pragma unroll
    for (int off = 16; off > 0; off >>= 1)
        acc += __shfl_down_sync(0xffffffffu, acc, off);

    __shared__ float wsum[8];
    __shared__ bool  isLast;
    const int lane = tid & 31, wid = tid >> 5;
    if (lane == 0) wsum[wid] = acc;
    __syncthreads();
    if (tid < 8) {
        float v = wsum[tid];
        #pragma unroll
        for (int off = 4; off > 0; off >>= 1)
            v += __shfl_down_sync(0x000000ffu, v, off);
        if (tid == 0) {
            g_partials[b * TILESY + tile] = v;
            __threadfence();
            unsigned int old = atomicAdd(&g_count, 1u);
            isLast = (old == (unsigned)(NBLK - 1));
        }
    }
    __syncthreads();

    // ---- Fused deterministic final reduction (last block, fp64 fixed order) ----
    if (isLast) {
        __shared__ double ds[TPB];
        double a = 0.0;
        #pragma unroll
        for (int i = 0; i < NBLK / TPB; i++)
            a += (double)__ldcg(&g_partials[tid + i * TPB]);
        ds[tid] = a;
        __syncthreads();
        #pragma unroll
        for (int st = TPB / 2; st > 0; st >>= 1) {
            if (tid < st) ds[tid] += ds[tid + st];
            __syncthreads();
        }
        if (tid == 0) {
            out[0] = (float)(ds[0] / (double)NPIX);
            g_count = 0;   // self-reset for graph replay
        }
    }
}

extern "C" void kernel_launch(void* const* d_in, const int* in_sizes, int n_in,
                              void* d_out, int out_size)
{
    const float* pred = (const float*)d_in[0];
    const float* tgt  = (const float*)d_in[1];
    float* out = (float*)d_out;

    dim3 grid(TILESY, B);   // (16, 32) = 512 blocks
    edge_loss_fused<<<grid, TPB>>>(pred, tgt, out);
}

// round 15
// speedup vs baseline: 1.2010x; 1.0089x over previous
#include <cuda_runtime.h>
#include <cuda_bf16.h>
#include <math.h>

// pred/target: (32, 3, 512, 512) fp32 -> scalar fp32 mean |sobel(gray(p)) - sobel(gray(t))|
#define B      32
#define H      512
#define W      512
#define PLANE  (H * W)
#define IMG    (3 * PLANE)
#define NPIX   (B * PLANE)            // 8388608

#define RT     32                     // rows per CTA tile
#define TILESY (H / RT)               // 16
#define NBLK   (B * TILESY)           // 512
#define TPB    256
#define SROW   520                    // smem row stride (floats); data at [4..515], zeros at 3/516

__device__ float        g_partials[NBLK];
__device__ unsigned int g_count = 0;

__device__ __forceinline__ float fsqrt_approx(float x) {
    float r; asm("sqrt.approx.f32 %0, %1;" : "=f"(r) : "f"(x)); return r;
}

// 3-channel float4 load for one row quad (zero-filled outside image).
__device__ __forceinline__ void ldg3(const float* __restrict__ img, int gy, int q,
                                     float4& r, float4& g, float4& bl)
{
    if ((unsigned)gy < (unsigned)H) {
        const float* p = img + (size_t)gy * W + 4 * q;
        r  = *(const float4*)p;
        g  = *(const float4*)(p + PLANE);
        bl = *(const float4*)(p + 2 * PLANE);
    } else {
        r = g = bl = make_float4(0.f, 0.f, 0.f, 0.f);
    }
}

__device__ __forceinline__ float4 gray4(float4 r, float4 g, float4 bl)
{
    float4 v;
    v.x = 0.299f * r.x + 0.587f * g.x + 0.114f * bl.x;
    v.y = 0.299f * r.y + 0.587f * g.y + 0.114f * bl.y;
    v.z = 0.299f * r.z + 0.587f * g.z + 0.114f * bl.z;
    v.w = 0.299f * r.w + 0.587f * g.w + 0.114f * bl.w;
    return v;
}

// Horizontal separable partials at column c of a staged gray row.
__device__ __forceinline__ void rdrow(const float* __restrict__ base, int c,
                                      float& hx, float& hs)
{
    float l  = base[3 + c];
    float m  = base[4 + c];
    float rr = base[5 + c];
    hx = rr - l;                 // [-1, 0, 1]
    hs = l + 2.f * m + rr;       // [ 1, 2, 1]
}

__global__ __launch_bounds__(TPB, 4) void edge_loss_fused(
    const float* __restrict__ pred, const float* __restrict__ tgt,
    float* __restrict__ out)
{
    // Ring: [img 0/1][slot 0/1][SROW]  (8.3 KB)
    __shared__ float ring[4 * SROW];

    const int tile = blockIdx.x;
    const int b    = blockIdx.y;
    const int gy0  = tile * RT;
    const int tid  = threadIdx.x;

    // Serpentine sweep: even tiles top-down, odd tiles bottom-up.
    // Both touches of each shared boundary row then occur at the same
    // execution phase across neighboring tiles -> halo re-reads hit L2.
    // Load-step k (k = 0..RT+1) fetches row ystart + k*ystep.
    // Sobel is sweep-direction agnostic: ex y-profile [1,2,1] is symmetric,
    // ey only enters squared.
    const bool rev    = (tile & 1);
    const int  ystart = rev ? (gy0 + RT) : (gy0 - 1);
    const int  ystep  = rev ? -1 : 1;

    // Staging role: thread stages quad q of image im.
    const int q  = tid & 127;
    const int im = tid >> 7;
    const float* simg = (im ? tgt : pred) + (size_t)b * IMG;

    // x-halo zeros (never overwritten; STS writes only [4..515]).
    if (tid < 4) { ring[tid * SROW + 3] = 0.f; ring[tid * SROW + 516] = 0.f; }

    // ---- Prologue: load-steps 0 -> slot 1, 1 -> slot 0; prefetch step 2 ----
    {
        float4 r, g, bl;
        ldg3(simg, ystart, q, r, g, bl);
        *(float4*)(ring + ((im << 1) | 1) * SROW + 4 + 4 * q) = gray4(r, g, bl);
        ldg3(simg, ystart + ystep, q, r, g, bl);
        *(float4*)(ring + ((im << 1) | 0) * SROW + 4 + 4 * q) = gray4(r, g, bl);
    }
    float4 fr, fg, fb;
    ldg3(simg, ystart + 2 * ystep, q, fr, fg, fb);
    __syncthreads();

    // ---- Build rolling windows for load-steps 0 and 1.
    //      Combos j: img = j>>1, col = (j&1) ? tid+256 : tid ----
    const int c0 = tid, c1 = tid + 256;
    float hx0[4], hx1[4], hs0[4], hs1[4];
    #pragma unroll
    for (int j = 0; j < 4; j++) {
        const int ib = (j >> 1) << 1;
        const int c  = (j & 1) ? c1 : c0;
        rdrow(ring + (ib | 1) * SROW, c, hx0[j], hs0[j]);   // step 0 (slot 1)
        rdrow(ring + (ib | 0) * SROW, c, hx1[j], hs1[j]);   // step 1 (slot 0)
    }
    __syncthreads();   // all reads of slot 1 done before iter 0 overwrites it

    // ---- Pipelined mainloop: STS(step r+2) -> LDG(step r+3) -> bar -> compute ----
    float acc = 0.f;
    #pragma unroll 2
    for (int r = 0; r < RT; r++) {
        const int s = (r + 1) & 1;
        *(float4*)(ring + ((im << 1) | s) * SROW + 4 + 4 * q) = gray4(fr, fg, fb);
        if (r < RT - 1)
            ldg3(simg, ystart + (r + 3) * ystep, q, fr, fg, fb);
        __syncthreads();

        float mag[4];
        #pragma unroll
        for (int j = 0; j < 4; j++) {
            const float* bnew = ring + ((((j >> 1) << 1)) | s) * SROW;
            const int c = (j & 1) ? c1 : c0;
            float hx2, hs2;
            rdrow(bnew, c, hx2, hs2);
            float ex = hx0[j] + 2.f * hx1[j] + hx2;
            float ey = hs2 - hs0[j];      // sign flips on rev sweep; squared below
            mag[j] = fsqrt_approx(ex * ex + ey * ey);
            hx0[j] = hx1[j]; hx1[j] = hx2;
            hs0[j] = hs1[j]; hs1[j] = hs2;
        }
        acc += fabsf(mag[0] - mag[2]) + fabsf(mag[1] - mag[3]);
    }

    // ---- Block reduction (fixed order) ----
    #pragma unroll
    for (int off = 16; off > 0; off >>= 1)
        acc += __shfl_down_sync(0xffffffffu, acc, off);

    __shared__ float wsum[8];
    __shared__ bool  isLast;
    const int lane = tid & 31, wid = tid >> 5;
    if (lane == 0) wsum[wid] = acc;
    __syncthreads();
    if (tid < 8) {
        float v = wsum[tid];
        #pragma unroll
        for (int off = 4; off > 0; off >>= 1)
            v += __shfl_down_sync(0x000000ffu, v, off);
        if (tid == 0) {
            g_partials[b * TILESY + tile] = v;
            __threadfence();
            unsigned int old = atomicAdd(&g_count, 1u);
            isLast = (old == (unsigned)(NBLK - 1));
        }
    }
    __syncthreads();

    // ---- Fused deterministic final reduction (last block, fp64 fixed order) ----
    if (isLast) {
        __shared__ double ds[TPB];
        double a = 0.0;
        #pragma unroll
        for (int i = 0; i < NBLK / TPB; i++)
            a += (double)__ldcg(&g_partials[tid + i * TPB]);
        ds[tid] = a;
        __syncthreads();
        #pragma unroll
        for (int st = TPB / 2; st > 0; st >>= 1) {
            if (tid < st) ds[tid] += ds[tid + st];
            __syncthreads();
        }
        if (tid == 0) {
            out[0] = (float)(ds[0] / (double)NPIX);
            g_count = 0;   // self-reset for graph replay
        }
    }
}

extern "C" void kernel_launch(void* const* d_in, const int* in_sizes, int n_in,
                              void* d_out, int out_size)
{
    const float* pred = (const float*)d_in[0];
    const float* tgt  = (const float*)d_in[1];
    float* out = (float*)d_out;

    dim3 grid(TILESY, B);   // (16, 32) = 512 blocks — fully resident in one wave
    edge_loss_fused<<<grid, TPB>>>(pred, tgt, out);
}

// round 16
// speedup vs baseline: 1.2247x; 1.0198x over previous
#include <cuda_runtime.h>
#include <cuda_bf16.h>
#include <math.h>

// pred/target: (32, 3, 512, 512) fp32 -> scalar fp32 mean |sobel(gray(p)) - sobel(gray(t))|
#define B      32
#define H      512
#define W      512
#define PLANE  (H * W)
#define IMG    (3 * PLANE)
#define NPIX   (B * PLANE)            // 8388608

#define RT     32                     // rows per CTA tile
#define TILESY (H / RT)               // 16
#define NBLK   (B * TILESY)           // 512
#define TPB    256
#define SROW   520                    // smem row stride (floats); data at [4..515], zeros at 3/516

__device__ float        g_partials[NBLK];
__device__ unsigned int g_count = 0;

__device__ __forceinline__ float fsqrt_approx(float x) {
    float r; asm("sqrt.approx.f32 %0, %1;" : "=f"(r) : "f"(x)); return r;
}

// 3-channel float4 load for one row quad (zero-filled outside image).
// stream=true  -> evict-first (.cs): row is read exactly once chip-wide.
// stream=false -> default (.ca): boundary rows shared with a neighbor tile,
//                 keep them L2-resident for the second reader.
__device__ __forceinline__ void ldg3(const float* __restrict__ img, int gy, int q,
                                     float4& r, float4& g, float4& bl, bool stream)
{
    if ((unsigned)gy < (unsigned)H) {
        const float* p = img + (size_t)gy * W + 4 * q;
        if (stream) {
            r  = __ldcs((const float4*)p);
            g  = __ldcs((const float4*)(p + PLANE));
            bl = __ldcs((const float4*)(p + 2 * PLANE));
        } else {
            r  = *(const float4*)p;
            g  = *(const float4*)(p + PLANE);
            bl = *(const float4*)(p + 2 * PLANE);
        }
    } else {
        r = g = bl = make_float4(0.f, 0.f, 0.f, 0.f);
    }
}

__device__ __forceinline__ float4 gray4(float4 r, float4 g, float4 bl)
{
    float4 v;
    v.x = 0.299f * r.x + 0.587f * g.x + 0.114f * bl.x;
    v.y = 0.299f * r.y + 0.587f * g.y + 0.114f * bl.y;
    v.z = 0.299f * r.z + 0.587f * g.z + 0.114f * bl.z;
    v.w = 0.299f * r.w + 0.587f * g.w + 0.114f * bl.w;
    return v;
}

// Horizontal separable partials at column c of a staged gray row.
__device__ __forceinline__ void rdrow(const float* __restrict__ base, int c,
                                      float& hx, float& hs)
{
    float l  = base[3 + c];
    float m  = base[4 + c];
    float rr = base[5 + c];
    hx = rr - l;                 // [-1, 0, 1]
    hs = l + 2.f * m + rr;       // [ 1, 2, 1]
}

__global__ __launch_bounds__(TPB, 4) void edge_loss_fused(
    const float* __restrict__ pred, const float* __restrict__ tgt,
    float* __restrict__ out)
{
    // Ring: [img 0/1][slot 0/1][SROW]  (8.3 KB)
    __shared__ float ring[4 * SROW];

    const int tile = blockIdx.x;
    const int b    = blockIdx.y;
    const int gy0  = tile * RT;
    const int tid  = threadIdx.x;

    // Serpentine sweep: even tiles top-down, odd tiles bottom-up, so both
    // touches of each shared boundary row occur at the same execution phase.
    // Sobel is sweep-direction agnostic (ex y-profile symmetric; ey squared).
    const bool rev    = (tile & 1);
    const int  ystart = rev ? (gy0 + RT) : (gy0 - 1);
    const int  ystep  = rev ? -1 : 1;

    // Staging role: thread stages quad q of image im.
    const int q  = tid & 127;
    const int im = tid >> 7;
    const float* simg = (im ? tgt : pred) + (size_t)b * IMG;

    // x-halo zeros (never overwritten; STS writes only [4..515]).
    if (tid < 4) { ring[tid * SROW + 3] = 0.f; ring[tid * SROW + 516] = 0.f; }

    // Load-step k fetches row ystart + k*ystep; steps 0,1,RT,RT+1 are rows
    // shared with a neighboring tile -> default policy; steps 2..RT-1 are
    // single-use -> streaming.
    // ---- Prologue: steps 0 -> slot 1, 1 -> slot 0; prefetch step 2 ----
    {
        float4 r, g, bl;
        ldg3(simg, ystart, q, r, g, bl, false);
        *(float4*)(ring + ((im << 1) | 1) * SROW + 4 + 4 * q) = gray4(r, g, bl);
        ldg3(simg, ystart + ystep, q, r, g, bl, false);
        *(float4*)(ring + ((im << 1) | 0) * SROW + 4 + 4 * q) = gray4(r, g, bl);
    }
    float4 fr, fg, fb;
    ldg3(simg, ystart + 2 * ystep, q, fr, fg, fb, true);
    __syncthreads();

    // ---- Build rolling windows for load-steps 0 and 1.
    //      Combos j: img = j>>1, col = (j&1) ? tid+256 : tid ----
    const int c0 = tid, c1 = tid + 256;
    float hx0[4], hx1[4], hs0[4], hs1[4];
    #pragma unroll
    for (int j = 0; j < 4; j++) {
        const int ib = (j >> 1) << 1;
        const int c  = (j & 1) ? c1 : c0;
        rdrow(ring + (ib | 1) * SROW, c, hx0[j], hs0[j]);   // step 0 (slot 1)
        rdrow(ring + (ib | 0) * SROW, c, hx1[j], hs1[j]);   // step 1 (slot 0)
    }
    __syncthreads();   // all reads of slot 1 done before iter 0 overwrites it

    // ---- Pipelined mainloop: STS(step r+2) -> LDG(step r+3) -> bar -> compute ----
    float acc = 0.f;
    #pragma unroll 2
    for (int r = 0; r < RT; r++) {
        const int s = (r + 1) & 1;
        *(float4*)(ring + ((im << 1) | s) * SROW + 4 + 4 * q) = gray4(fr, fg, fb);
        if (r < RT - 1)
            ldg3(simg, ystart + (r + 3) * ystep, q, fr, fg, fb,
                 /*stream=*/(r + 3) <= RT - 1);   // steps RT,RT+1 keep .ca
        __syncthreads();

        float mag[4];
        #pragma unroll
        for (int j = 0; j < 4; j++) {
            const float* bnew = ring + ((((j >> 1) << 1)) | s) * SROW;
            const int c = (j & 1) ? c1 : c0;
            float hx2, hs2;
            rdrow(bnew, c, hx2, hs2);
            float ex = hx0[j] + 2.f * hx1[j] + hx2;
            float ey = hs2 - hs0[j];      // sign flips on rev sweep; squared below
            mag[j] = fsqrt_approx(ex * ex + ey * ey);
            hx0[j] = hx1[j]; hx1[j] = hx2;
            hs0[j] = hs1[j]; hs1[j] = hs2;
        }
        acc += fabsf(mag[0] - mag[2]) + fabsf(mag[1] - mag[3]);
    }

    // ---- Block reduction (fixed order) ----
    #pragma unroll
    for (int off = 16; off > 0; off >>= 1)
        acc += __shfl_down_sync(0xffffffffu, acc, off);

    __shared__ float wsum[8];
    __shared__ bool  isLast;
    const int lane = tid & 31, wid = tid >> 5;
    if (lane == 0) wsum[wid] = acc;
    __syncthreads();
    if (tid < 8) {
        float v = wsum[tid];
        #pragma unroll
        for (int off = 4; off > 0; off >>= 1)
            v += __shfl_down_sync(0x000000ffu, v, off);
        if (tid == 0) {
            g_partials[b * TILESY + tile] = v;
            __threadfence();
            unsigned int old = atomicAdd(&g_count, 1u);
            isLast = (old == (unsigned)(NBLK - 1));
        }
    }
    __syncthreads();

    // ---- Fused deterministic final reduction (last block, fp64 fixed order) ----
    if (isLast) {
        __shared__ double ds[TPB];
        double a = 0.0;
        #pragma unroll
        for (int i = 0; i < NBLK / TPB; i++)
            a += (double)__ldcg(&g_partials[tid + i * TPB]);
        ds[tid] = a;
        __syncthreads();
        #pragma unroll
        for (int st = TPB / 2; st > 0; st >>= 1) {
            if (tid < st) ds[tid] += ds[tid + st];
            __syncthreads();
        }
        if (tid == 0) {
            out[0] = (float)(ds[0] / (double)NPIX);
            g_count = 0;   // self-reset for graph replay
        }
    }
}

extern "C" void kernel_launch(void* const* d_in, const int* in_sizes, int n_in,
                              void* d_out, int out_size)
{
    const float* pred = (const float*)d_in[0];
    const float* tgt  = (const float*)d_in[1];
    float* out = (float*)d_out;

    dim3 grid(TILESY, B);   // (16, 32) = 512 blocks — fully resident in one wave
    edge_loss_fused<<<grid, TPB>>>(pred, tgt, out);
}

// round 17
// speedup vs baseline: 1.2536x; 1.0236x over previous
#include <cuda_runtime.h>
#include <cuda_bf16.h>
#include <math.h>

// pred/target: (32, 3, 512, 512) fp32 -> scalar fp32 mean |sobel(gray(p)) - sobel(gray(t))|
#define B      32
#define H      512
#define W      512
#define PLANE  (H * W)
#define IMG    (3 * PLANE)
#define NPIX   (B * PLANE)            // 8388608

#define RT     32                     // rows per CTA tile
#define TILESY (H / RT)               // 16
#define NBLK   (B * TILESY)           // 512
#define TPB    256
#define SROW   520                    // smem row stride (floats); data at [4..515], zeros at 3/516

__device__ float        g_partials[NBLK];
__device__ unsigned int g_count = 0;

__device__ __forceinline__ float fsqrt_approx(float x) {
    float r; asm("sqrt.approx.f32 %0, %1;" : "=f"(r) : "f"(x)); return r;
}

// 3-channel float4 load for one row quad (zero-filled outside image).
// All offsets 32-bit: gy*W + 4*q < 2^18, PLANE offsets < 2^20.
// stream=true  -> evict-first (.cs): row read exactly once chip-wide.
// stream=false -> default (.ca): boundary rows shared with a neighbor tile.
__device__ __forceinline__ void ldg3(const float* __restrict__ img, int gy, int q,
                                     float4& r, float4& g, float4& bl, bool stream)
{
    if ((unsigned)gy < (unsigned)H) {
        const float* p = img + (unsigned)(gy * W + 4 * q);
        if (stream) {
            r  = __ldcs((const float4*)p);
            g  = __ldcs((const float4*)(p + PLANE));
            bl = __ldcs((const float4*)(p + 2 * PLANE));
        } else {
            r  = *(const float4*)p;
            g  = *(const float4*)(p + PLANE);
            bl = *(const float4*)(p + 2 * PLANE);
        }
    } else {
        r = g = bl = make_float4(0.f, 0.f, 0.f, 0.f);
    }
}

__device__ __forceinline__ float4 gray4(float4 r, float4 g, float4 bl)
{
    float4 v;
    v.x = 0.299f * r.x + 0.587f * g.x + 0.114f * bl.x;
    v.y = 0.299f * r.y + 0.587f * g.y + 0.114f * bl.y;
    v.z = 0.299f * r.z + 0.587f * g.z + 0.114f * bl.z;
    v.w = 0.299f * r.w + 0.587f * g.w + 0.114f * bl.w;
    return v;
}

// Horizontal separable partials at column c of a staged gray row.
__device__ __forceinline__ void rdrow(const float* __restrict__ base, int c,
                                      float& hx, float& hs)
{
    float l  = base[3 + c];
    float m  = base[4 + c];
    float rr = base[5 + c];
    hx = rr - l;                 // [-1, 0, 1]
    hs = l + 2.f * m + rr;       // [ 1, 2, 1]
}

__global__ __launch_bounds__(TPB, 5) void edge_loss_fused(
    const float* __restrict__ pred, const float* __restrict__ tgt,
    float* __restrict__ out)
{
    // Ring: [img 0/1][slot 0/1][SROW]  (8.3 KB)
    __shared__ float ring[4 * SROW];

    const int tile = blockIdx.x;
    const int b    = blockIdx.y;
    const int gy0  = tile * RT;
    const int tid  = threadIdx.x;

    // Serpentine sweep: even tiles top-down, odd tiles bottom-up, so both
    // touches of each shared boundary row occur at the same execution phase.
    // Sobel is sweep-direction agnostic (ex y-profile symmetric; ey squared).
    const bool rev    = (tile & 1);
    const int  ystart = rev ? (gy0 + RT) : (gy0 - 1);
    const int  ystep  = rev ? -1 : 1;

    // Staging role: thread stages quad q of image im.
    const int q  = tid & 127;
    const int im = tid >> 7;
    const float* simg = (im ? tgt : pred) + (size_t)b * IMG;

    // x-halo zeros (never overwritten; STS writes only [4..515]).
    if (tid < 4) { ring[tid * SROW + 3] = 0.f; ring[tid * SROW + 516] = 0.f; }

    // Load-step k fetches row ystart + k*ystep; steps 0,1,RT,RT+1 are shared
    // with a neighboring tile -> default policy; steps 2..RT-1 -> streaming.
    // ---- Prologue: steps 0 -> slot 1, 1 -> slot 0; prefetch step 2 ----
    {
        float4 r, g, bl;
        ldg3(simg, ystart, q, r, g, bl, false);
        *(float4*)(ring + ((im << 1) | 1) * SROW + 4 + 4 * q) = gray4(r, g, bl);
        ldg3(simg, ystart + ystep, q, r, g, bl, false);
        *(float4*)(ring + ((im << 1) | 0) * SROW + 4 + 4 * q) = gray4(r, g, bl);
    }
    float4 fr, fg, fb;
    ldg3(simg, ystart + 2 * ystep, q, fr, fg, fb, true);
    __syncthreads();

    // ---- Build rolling windows for load-steps 0 and 1.
    //      Combos j: img = j>>1, col = (j&1) ? tid+256 : tid ----
    const int c0 = tid, c1 = tid + 256;
    float hx0[4], hx1[4], hs0[4], hs1[4];
    #pragma unroll
    for (int j = 0; j < 4; j++) {
        const int ib = (j >> 1) << 1;
        const int c  = (j & 1) ? c1 : c0;
        rdrow(ring + (ib | 1) * SROW, c, hx0[j], hs0[j]);   // step 0 (slot 1)
        rdrow(ring + (ib | 0) * SROW, c, hx1[j], hs1[j]);   // step 1 (slot 0)
    }
    __syncthreads();   // all reads of slot 1 done before iter 0 overwrites it

    // ---- Pipelined mainloop: STS(step r+2) -> LDG(step r+3) -> bar -> compute ----
    float acc = 0.f;
    #pragma unroll 2
    for (int r = 0; r < RT; r++) {
        const int s = (r + 1) & 1;
        *(float4*)(ring + ((im << 1) | s) * SROW + 4 + 4 * q) = gray4(fr, fg, fb);
        if (r < RT - 1)
            ldg3(simg, ystart + (r + 3) * ystep, q, fr, fg, fb,
                 /*stream=*/(r + 3) <= RT - 1);   // steps RT,RT+1 keep .ca
        __syncthreads();

        float mag[4];
        #pragma unroll
        for (int j = 0; j < 4; j++) {
            const float* bnew = ring + ((((j >> 1) << 1)) | s) * SROW;
            const int c = (j & 1) ? c1 : c0;
            float hx2, hs2;
            rdrow(bnew, c, hx2, hs2);
            float ex = hx0[j] + 2.f * hx1[j] + hx2;
            float ey = hs2 - hs0[j];      // sign flips on rev sweep; squared below
            mag[j] = fsqrt_approx(ex * ex + ey * ey);
            hx0[j] = hx1[j]; hx1[j] = hx2;
            hs0[j] = hs1[j]; hs1[j] = hs2;
        }
        acc += fabsf(mag[0] - mag[2]) + fabsf(mag[1] - mag[3]);
    }

    // ---- Block reduction (fixed order) ----
    #pragma unroll
    for (int off = 16; off > 0; off >>= 1)
        acc += __shfl_down_sync(0xffffffffu, acc, off);

    __shared__ float wsum[8];
    __shared__ bool  isLast;
    const int lane = tid & 31, wid = tid >> 5;
    if (lane == 0) wsum[wid] = acc;
    __syncthreads();
    if (tid < 8) {
        float v = wsum[tid];
        #pragma unroll
        for (int off = 4; off > 0; off >>= 1)
            v += __shfl_down_sync(0x000000ffu, v, off);
        if (tid == 0) {
            g_partials[b * TILESY + tile] = v;
            __threadfence();
            unsigned int old = atomicAdd(&g_count, 1u);
            isLast = (old == (unsigned)(NBLK - 1));
        }
    }
    __syncthreads();

    // ---- Fused deterministic final reduction (last block, fp64 fixed order) ----
    if (isLast) {
        __shared__ double ds[TPB];
        double a = 0.0;
        #pragma unroll
        for (int i = 0; i < NBLK / TPB; i++)
            a += (double)__ldcg(&g_partials[tid + i * TPB]);
        ds[tid] = a;
        __syncthreads();
        #pragma unroll
        for (int st = TPB / 2; st > 0; st >>= 1) {
            if (tid < st) ds[tid] += ds[tid + st];
            __syncthreads();
        }
        if (tid == 0) {
            out[0] = (float)(ds[0] / (double)NPIX);
            g_count = 0;   // self-reset for graph replay
        }
    }
}

extern "C" void kernel_launch(void* const* d_in, const int* in_sizes, int n_in,
                              void* d_out, int out_size)
{
    const float* pred = (const float*)d_in[0];
    const float* tgt  = (const float*)d_in[1];
    float* out = (float*)d_out;

    dim3 grid(TILESY, B);   // (16, 32) = 512 blocks — fully resident in one wave
    edge_loss_fused<<<grid, TPB>>>(pred, tgt, out);
}